// round 13
// baseline (speedup 1.0000x reference)
#include <cuda_runtime.h>
#include <cstdint>

#define FULLMASK 0xffffffffu
typedef unsigned long long ull;

static constexpr int Hh     = 5;
static constexpr int Tt     = 512;
static constexpr int Bb     = 8192;
static constexpr int CHUNK  = 8;            // timesteps per smem chunk
static constexpr int NCHUNK = Tt / CHUNK;   // 64
static constexpr int EPW    = 16;           // elements per warp (2 lanes each)
static constexpr int WPB    = 4;            // warps per block (one per SMSP!)
static constexpr int BLOCK  = 32 * WPB;     // 128
static constexpr int EPB    = EPW * WPB;    // 64 elements per block
static constexpr int GRID   = Bb / EPB;     // 128 (exact)
static constexpr int ROWF   = Tt * Hh;      // 2560
static constexpr int CH_FL  = CHUNK * Hh;   // 40 floats per element per chunk

// ---------- packed f32x2 helpers ----------
__device__ __forceinline__ ull pack2(float lo, float hi) {
    ull r; asm("mov.b64 %0, {%1, %2};" : "=l"(r) : "f"(lo), "f"(hi)); return r;
}
__device__ __forceinline__ void unpack2(ull v, float& lo, float& hi) {
    asm("mov.b64 {%0, %1}, %2;" : "=f"(lo), "=f"(hi) : "l"(v));
}
__device__ __forceinline__ ull fma2(ull a, ull b, ull c) {
    ull d; asm("fma.rn.f32x2 %0, %1, %2, %3;" : "=l"(d) : "l"(a), "l"(b), "l"(c));
    return d;
}
__device__ __forceinline__ float tanh_fast(float x) {
    float y; asm("tanh.approx.f32 %0, %1;" : "=f"(y) : "f"(x)); return y;
}

// ============================================================================
// Fused LSTM + head. 4 warps/CTA (one per SMSP, guaranteed spread), each warp
// independently owns 16 elements, 2 lanes/element (all 32 lanes busy).
// lane = 2*e + role.  role0 owns pair-rows (i_s, g_s) for s=0..4,
//                     role1 owns (f_s, o_s) + state c_s, hs_s = 2*h_s.
// Sigmoid folding (proven, rel_err 7.2e-7): accs for i/f/o rows hold z/2,
// g rows hold z; internal state hs = 2h.  Folded scales:
//   W_ih: i/f/o *0.5, g *1 ;  W_hh: i/f/o *0.25, g *0.5 ; biases likewise.
// Per-component epilogue (uniform across roles):
//   T0 = tanh(acc.lo) [Ti|Tf],  T1 = tanh(acc.hi) [Tg|To]
//   pa = fma(T0,T1,T1)  -> role0: 2ig ;  pp = shfl(pa, lane&~1)
//   u  = fma(T0,c,c)    -> role1: 2fc ;  c = 0.5*u + 0.5*pp
//   Tc = tanh(c); hs = fma(T1,Tc,Tc)  -> role1: new 2h
// Cross-lane: 5 h-shfl (from lane|1) + 5 p-shfl (from lane&~1) per step.
// ============================================================================
__global__ void __launch_bounds__(BLOCK)
fused_kernel(const float* __restrict__ x,
             const float* __restrict__ W_ih, const float* __restrict__ W_hh,
             const float* __restrict__ b_ih, const float* __restrict__ b_hh,
             const float* __restrict__ W1, const float* __restrict__ b1,
             const float* __restrict__ W2, const float* __restrict__ b2,
             const float* __restrict__ W3, const float* __restrict__ b3,
             float* __restrict__ out)
{
    __shared__ ull   sx[WPB][2][CHUNK][EPW][Hh];  // per-warp x dup pairs: 40 KB
    __shared__ float sW1[32 * 5], sb1[32], sb2[32], sb3[5];
    __shared__ float sW2[32 * 33];                // padded rows
    __shared__ float sW3[5 * 33];
    __shared__ float hres[WPB][EPW * Hh];

    const int tid  = threadIdx.x;
    const int warp = tid >> 5;
    const int lane = tid & 31;
    const int e    = lane >> 1;
    const int role = lane & 1;

    const int base = blockIdx.x * EPB + warp * EPW;
    const int gb   = base + e;

    // ---- per-lane packed weights: 5 pair-rows x (5 x-cols + 5 h-cols) ----
    const int rlo = 5 * role;                 // +0 | +5   (i_s | f_s)
    const int rhi = 10 + 5 * role;            // +10 | +15 (g_s | o_s)
    const float xhi = role ? 0.5f : 1.0f;     // g unscaled, o *0.5
    const float hhi = role ? 0.25f : 0.5f;

    ull wx[5][5], wh[5][5], bias[5];
#pragma unroll
    for (int s = 0; s < 5; ++s) {
#pragma unroll
        for (int k = 0; k < 5; ++k) {
            wx[s][k] = pack2(0.50f * W_ih[(s + rlo) * 5 + k],
                             xhi   * W_ih[(s + rhi) * 5 + k]);
            wh[s][k] = pack2(0.25f * W_hh[(s + rlo) * 5 + k],
                             hhi   * W_hh[(s + rhi) * 5 + k]);
        }
        bias[s] = pack2(0.5f * (b_ih[s + rlo] + b_hh[s + rlo]),
                        xhi  * (b_ih[s + rhi] + b_hh[s + rhi]));
    }

    // ---- head weights to smem (block-cooperative, one-time) ----
    for (int i = tid; i < 160; i += BLOCK) sW1[i] = W1[i];
    for (int i = tid; i < 1024; i += BLOCK) sW2[(i >> 5) * 33 + (i & 31)] = W2[i];
    for (int i = tid; i < 160; i += BLOCK) sW3[(i >> 5) * 33 + (i & 31)] = W3[i];
    if (tid < 32) { sb1[tid] = b1[tid]; sb2[tid] = b2[tid]; }
    if (tid < 5)  sb3[tid] = b3[tid];
    __syncthreads();   // only cross-warp sync; loop below is warp-independent

    // ---- staging: lane covers floats [role*20, role*20+20) of its element ----
    const int lo = role * 20;                 // 16B-aligned (80 B rows)

#define STAGE_LDG(C)                                                          \
    do { const float* src = x + gb * ROWF + (C) * CH_FL + lo;                 \
        pf0 = *(const float4*)(src);                                          \
        pf1 = *(const float4*)(src + 4);                                      \
        pf2 = *(const float4*)(src + 8);                                      \
        pf3 = *(const float4*)(src + 12);                                     \
        pf4 = *(const float4*)(src + 16);                                     \
    } while (0)

#define STAGE_STS(BUF)                                                        \
    do { const float* ap[5] = {&pf0.x, &pf1.x, &pf2.x, &pf3.x, &pf4.x};       \
        _Pragma("unroll")                                                     \
        for (int j = 0; j < 20; ++j) {                                        \
            const float v = ap[j >> 2][j & 3];                                \
            const int f = lo + j, t = f / 5, k = f - 5 * t;                   \
            sx[warp][BUF][t][e][k] = pack2(v, v); }                           \
    } while (0)

    float4 pf0, pf1, pf2, pf3, pf4;
    STAGE_LDG(0);
    STAGE_STS(0);
    __syncwarp();

    float c[5]  = {0.f, 0.f, 0.f, 0.f, 0.f};
    float hs[5] = {0.f, 0.f, 0.f, 0.f, 0.f};  // role1: 2*h_s

    // per-component epilogue (uniform instructions for both roles)
#define EPI(S, ACC)                                                           \
    do { float z0, z1; unpack2(ACC, z0, z1);                                  \
        const float T0 = tanh_fast(z0);           /* Ti | Tf */               \
        const float T1 = tanh_fast(z1);           /* Tg | To */               \
        const float pa = fmaf(T0, T1, T1);        /* role0: 2ig */            \
        const float pp = __shfl_sync(FULLMASK, pa, lane & ~1);                \
        const float u  = fmaf(T0, c[S], c[S]);    /* role1: 2fc */            \
        c[S] = fmaf(0.5f, u, 0.5f * pp);          /* role1: new c */          \
        const float Tc = tanh_fast(c[S]);                                     \
        hs[S] = fmaf(T1, Tc, Tc);                 /* role1: new 2h */         \
    } while (0)

    for (int ch = 0; ch < NCHUNK; ++ch) {
        if (ch + 1 < NCHUNK) STAGE_LDG(ch + 1);

        const int buf = ch & 1;
#pragma unroll
        for (int tl = 0; tl < CHUNK; ++tl) {
            const ull* xr = &sx[warp][buf][tl][e][0];
            ull a0 = bias[0], a1 = bias[1], a2 = bias[2], a3 = bias[3], a4 = bias[4];

            // x-projection (independent of h; schedulable into MUFU gaps)
#pragma unroll
            for (int k = 0; k < 5; ++k) {
                const ull xk = xr[k];                    // dup pair, LDS.64
                a0 = fma2(wx[0][k], xk, a0);
                a1 = fma2(wx[1][k], xk, a1);
                a2 = fma2(wx[2][k], xk, a2);
                a3 = fma2(wx[3][k], xk, a3);
                a4 = fma2(wx[4][k], xk, a4);
            }
            // h-projection (chain; h from partner role1 lane)
#pragma unroll
            for (int k = 0; k < 5; ++k) {
                const float hk = __shfl_sync(FULLMASK, hs[k], lane | 1);
                const ull hd = pack2(hk, hk);
                a0 = fma2(wh[0][k], hd, a0);
                a1 = fma2(wh[1][k], hd, a1);
                a2 = fma2(wh[2][k], hd, a2);
                a3 = fma2(wh[3][k], hd, a3);
                a4 = fma2(wh[4][k], hd, a4);
            }

            EPI(0, a0); EPI(1, a1); EPI(2, a2); EPI(3, a3); EPI(4, a4);
        }

        if (ch + 1 < NCHUNK) STAGE_STS((ch + 1) & 1);
        __syncwarp();
    }

    // ==================== fused head (per-warp) ====================
    if (role == 1) {
#pragma unroll
        for (int s = 0; s < 5; ++s)
            hres[warp][e * Hh + s] = 0.5f * hs[s] + x[gb * ROWF + (Tt - 1) * Hh + s];
    }
    __syncwarp();

#pragma unroll 4
    for (int ee = 0; ee < EPW; ++ee) {
        const int g = base + ee;
        float a1 = sb1[lane];
#pragma unroll
        for (int k = 0; k < 5; ++k)
            a1 = fmaf(sW1[lane * 5 + k], hres[warp][ee * Hh + k], a1);
        a1 = fmaxf(a1, 0.0f);

        float a2 = sb2[lane];
#pragma unroll
        for (int k = 0; k < 32; ++k)
            a2 = fmaf(sW2[lane * 33 + k], __shfl_sync(FULLMASK, a1, k), a2);
        a2 = fmaxf(a2, 0.0f);

        const int wrow = (lane < 5) ? lane : 0;
        float o = (lane < 5) ? sb3[lane] : 0.0f;
#pragma unroll
        for (int k = 0; k < 32; ++k)
            o = fmaf(sW3[wrow * 33 + k], __shfl_sync(FULLMASK, a2, k), o);

        if (lane < 5) out[g * Hh + lane] = o;
    }

#undef STAGE_LDG
#undef STAGE_STS
#undef EPI
}

// ============================================================================
extern "C" void kernel_launch(void* const* d_in, const int* in_sizes, int n_in,
                              void* d_out, int out_size) {
    const float* x    = (const float*)d_in[0];
    const float* W_ih = (const float*)d_in[1];
    const float* W_hh = (const float*)d_in[2];
    const float* b_ih = (const float*)d_in[3];
    const float* b_hh = (const float*)d_in[4];
    const float* W1   = (const float*)d_in[5];
    const float* b1   = (const float*)d_in[6];
    const float* W2   = (const float*)d_in[7];
    const float* b2   = (const float*)d_in[8];
    const float* W3   = (const float*)d_in[9];
    const float* b3   = (const float*)d_in[10];
    float* out = (float*)d_out;

    fused_kernel<<<GRID, BLOCK>>>(x, W_ih, W_hh, b_ih, b_hh,
                                  W1, b1, W2, b2, W3, b3, out);
    (void)in_sizes; (void)n_in; (void)out_size;
}

// round 14
// speedup vs baseline: 1.0419x; 1.0419x over previous
#include <cuda_runtime.h>
#include <cstdint>

#define FULLMASK 0xffffffffu
typedef unsigned long long ull;

static constexpr int Hh     = 5;
static constexpr int Tt     = 512;
static constexpr int Bb     = 8192;
static constexpr int CHUNK  = 8;            // timesteps per smem chunk
static constexpr int NCHUNK = Tt / CHUNK;   // 64
static constexpr int EPW    = 16;           // elements per warp (2 lanes each)
static constexpr int BLOCK  = 32;
static constexpr int GRID   = Bb / EPW;     // 512 (exact)
static constexpr int ROWF   = Tt * Hh;      // 2560
static constexpr int CH_FL  = CHUNK * Hh;   // 40 floats per element per chunk

// ---------- packed f32x2 helpers ----------
__device__ __forceinline__ ull pack2(float lo, float hi) {
    ull r; asm("mov.b64 %0, {%1, %2};" : "=l"(r) : "f"(lo), "f"(hi)); return r;
}
__device__ __forceinline__ void unpack2(ull v, float& lo, float& hi) {
    asm("mov.b64 {%0, %1}, %2;" : "=f"(lo), "=f"(hi) : "l"(v));
}
__device__ __forceinline__ ull fma2(ull a, ull b, ull c) {
    ull d; asm("fma.rn.f32x2 %0, %1, %2, %3;" : "=l"(d) : "l"(a), "l"(b), "l"(c));
    return d;
}
__device__ __forceinline__ float tanh_fast(float x) {
    float y; asm("tanh.approx.f32 %0, %1;" : "=f"(y) : "f"(x)); return y;
}

// ============================================================================
// Fused LSTM + head. One warp/CTA, 16 elements, 2 lanes/element.
// lane = 2*e + role.  role0 owns pair-rows (i_s, g_s),
//                     role1 owns (f_s, o_s) + state c_s, hs_s = 2*h_s.
// Sigmoid folding (proven, rel_err 7.2e-7): i/f/o accs hold z/2, g holds z;
// internal state hs = 2h.  W_ih: i/f/o *0.5, g *1; W_hh: i/f/o *0.25, g *0.5.
//
// R14 change: the step body is PHASE-SPLIT for ILP — all shfls issue together
// so their latencies overlap, x-projection runs under the h-shfl latency, and
// the 5 component epilogues advance in lockstep phases (10 tanh / 5 pa /
// 5 p-shfl / 5 c / 5 Tc / 5 hs) instead of 5 serial chains.
// ============================================================================
__global__ void __launch_bounds__(BLOCK)
fused_kernel(const float* __restrict__ x,
             const float* __restrict__ W_ih, const float* __restrict__ W_hh,
             const float* __restrict__ b_ih, const float* __restrict__ b_hh,
             const float* __restrict__ W1, const float* __restrict__ b1,
             const float* __restrict__ W2, const float* __restrict__ b2,
             const float* __restrict__ W3, const float* __restrict__ b3,
             float* __restrict__ out)
{
    __shared__ ull   sx[2][CHUNK][EPW][Hh];   // x dup pairs: 10240 B
    __shared__ float sW1[32 * 5], sb1[32], sb2[32], sb3[5];
    __shared__ float sW2[32 * 33];            // padded rows
    __shared__ float sW3[5 * 33];
    __shared__ float hres[EPW * Hh];

    const int lane = threadIdx.x;
    const int e    = lane >> 1;
    const int role = lane & 1;

    const int base = blockIdx.x * EPW;
    const int gb   = base + e;

    // ---- per-lane packed weights ----
    const int rlo = 5 * role;                 // +0 | +5   (i_s | f_s)
    const int rhi = 10 + 5 * role;            // +10 | +15 (g_s | o_s)
    const float xhi = role ? 0.5f : 1.0f;
    const float hhi = role ? 0.25f : 0.5f;

    ull wx[5][5], wh[5][5], bias[5];
#pragma unroll
    for (int s = 0; s < 5; ++s) {
#pragma unroll
        for (int k = 0; k < 5; ++k) {
            wx[s][k] = pack2(0.50f * W_ih[(s + rlo) * 5 + k],
                             xhi   * W_ih[(s + rhi) * 5 + k]);
            wh[s][k] = pack2(0.25f * W_hh[(s + rlo) * 5 + k],
                             hhi   * W_hh[(s + rhi) * 5 + k]);
        }
        bias[s] = pack2(0.5f * (b_ih[s + rlo] + b_hh[s + rlo]),
                        xhi  * (b_ih[s + rhi] + b_hh[s + rhi]));
    }

    // ---- head weights to smem (one-time) ----
    for (int i = lane; i < 160; i += BLOCK) sW1[i] = W1[i];
    for (int i = lane; i < 1024; i += BLOCK) sW2[(i >> 5) * 33 + (i & 31)] = W2[i];
    for (int i = lane; i < 160; i += BLOCK) sW3[(i >> 5) * 33 + (i & 31)] = W3[i];
    if (lane < 32) { sb1[lane] = b1[lane]; sb2[lane] = b2[lane]; }
    if (lane < 5)  sb3[lane] = b3[lane];

    // ---- staging: lane covers floats [role*20, role*20+20) of its element ----
    const int lo = role * 20;

#define STAGE_LDG(C)                                                          \
    do { const float* src = x + gb * ROWF + (C) * CH_FL + lo;                 \
        pf0 = *(const float4*)(src);                                          \
        pf1 = *(const float4*)(src + 4);                                      \
        pf2 = *(const float4*)(src + 8);                                      \
        pf3 = *(const float4*)(src + 12);                                     \
        pf4 = *(const float4*)(src + 16);                                     \
    } while (0)

#define STAGE_STS(BUF)                                                        \
    do { const float* ap[5] = {&pf0.x, &pf1.x, &pf2.x, &pf3.x, &pf4.x};       \
        _Pragma("unroll")                                                     \
        for (int j = 0; j < 20; ++j) {                                        \
            const float v = ap[j >> 2][j & 3];                                \
            const int f = lo + j, t = f / 5, k = f - 5 * t;                   \
            sx[BUF][t][e][k] = pack2(v, v); }                                 \
    } while (0)

    float4 pf0, pf1, pf2, pf3, pf4;
    STAGE_LDG(0);
    STAGE_STS(0);
    __syncwarp();

    float c[5]  = {0.f, 0.f, 0.f, 0.f, 0.f};
    float hs[5] = {0.f, 0.f, 0.f, 0.f, 0.f};  // role1: 2*h_s

    for (int ch = 0; ch < NCHUNK; ++ch) {
        if (ch + 1 < NCHUNK) STAGE_LDG(ch + 1);

        const int buf = ch & 1;
#pragma unroll
        for (int tl = 0; tl < CHUNK; ++tl) {
            const ull* xr = &sx[buf][tl][e][0];

            // -- phase 1: all h-shfls issue first (latencies overlap) --
            float hk[5];
#pragma unroll
            for (int k = 0; k < 5; ++k)
                hk[k] = __shfl_sync(FULLMASK, hs[k], lane | 1);

            // -- phase 2: x-projection runs under the shfl latency --
            ull a0 = bias[0], a1 = bias[1], a2 = bias[2], a3 = bias[3], a4 = bias[4];
#pragma unroll
            for (int k = 0; k < 5; ++k) {
                const ull xk = xr[k];                    // dup pair, LDS.64
                a0 = fma2(wx[0][k], xk, a0);
                a1 = fma2(wx[1][k], xk, a1);
                a2 = fma2(wx[2][k], xk, a2);
                a3 = fma2(wx[3][k], xk, a3);
                a4 = fma2(wx[4][k], xk, a4);
            }

            // -- phase 3: pack + h-projection --
            ull hd[5];
#pragma unroll
            for (int k = 0; k < 5; ++k) hd[k] = pack2(hk[k], hk[k]);
#pragma unroll
            for (int k = 0; k < 5; ++k) {
                a0 = fma2(wh[0][k], hd[k], a0);
                a1 = fma2(wh[1][k], hd[k], a1);
                a2 = fma2(wh[2][k], hd[k], a2);
                a3 = fma2(wh[3][k], hd[k], a3);
                a4 = fma2(wh[4][k], hd[k], a4);
            }

            // -- phase 4: epilogue, phase-split across all 5 components --
            const ull av[5] = {a0, a1, a2, a3, a4};
            float T0[5], T1[5];
#pragma unroll
            for (int s = 0; s < 5; ++s) {                // 10 tanh back-to-back
                float z0, z1; unpack2(av[s], z0, z1);
                T0[s] = tanh_fast(z0);                   // Ti | Tf
                T1[s] = tanh_fast(z1);                   // Tg | To
            }
            float pa[5];
#pragma unroll
            for (int s = 0; s < 5; ++s)                  // role0: 2ig
                pa[s] = fmaf(T0[s], T1[s], T1[s]);
            float pp[5];
#pragma unroll
            for (int s = 0; s < 5; ++s)                  // 5 shfls overlap
                pp[s] = __shfl_sync(FULLMASK, pa[s], lane & ~1);
#pragma unroll
            for (int s = 0; s < 5; ++s) {                // role1: new c
                const float u = fmaf(T0[s], c[s], c[s]); // 2fc
                c[s] = fmaf(0.5f, u, 0.5f * pp[s]);
            }
            float Tc[5];
#pragma unroll
            for (int s = 0; s < 5; ++s)                  // 5 tanh back-to-back
                Tc[s] = tanh_fast(c[s]);
#pragma unroll
            for (int s = 0; s < 5; ++s)                  // role1: new 2h
                hs[s] = fmaf(T1[s], Tc[s], Tc[s]);
        }

        if (ch + 1 < NCHUNK) STAGE_STS((ch + 1) & 1);
        __syncwarp();
    }

    // ==================== fused head ====================
    if (role == 1) {
#pragma unroll
        for (int s = 0; s < 5; ++s)
            hres[e * Hh + s] = 0.5f * hs[s] + x[gb * ROWF + (Tt - 1) * Hh + s];
    }
    __syncwarp();

#pragma unroll 4
    for (int ee = 0; ee < EPW; ++ee) {
        const int g = base + ee;
        float a1 = sb1[lane];
#pragma unroll
        for (int k = 0; k < 5; ++k)
            a1 = fmaf(sW1[lane * 5 + k], hres[ee * Hh + k], a1);
        a1 = fmaxf(a1, 0.0f);

        float a2 = sb2[lane];
#pragma unroll
        for (int k = 0; k < 32; ++k)
            a2 = fmaf(sW2[lane * 33 + k], __shfl_sync(FULLMASK, a1, k), a2);
        a2 = fmaxf(a2, 0.0f);

        const int wrow = (lane < 5) ? lane : 0;
        float o = (lane < 5) ? sb3[lane] : 0.0f;
#pragma unroll
        for (int k = 0; k < 32; ++k)
            o = fmaf(sW3[wrow * 33 + k], __shfl_sync(FULLMASK, a2, k), o);

        if (lane < 5) out[g * Hh + lane] = o;
    }

#undef STAGE_LDG
#undef STAGE_STS
}

// ============================================================================
extern "C" void kernel_launch(void* const* d_in, const int* in_sizes, int n_in,
                              void* d_out, int out_size) {
    const float* x    = (const float*)d_in[0];
    const float* W_ih = (const float*)d_in[1];
    const float* W_hh = (const float*)d_in[2];
    const float* b_ih = (const float*)d_in[3];
    const float* b_hh = (const float*)d_in[4];
    const float* W1   = (const float*)d_in[5];
    const float* b1   = (const float*)d_in[6];
    const float* W2   = (const float*)d_in[7];
    const float* b2   = (const float*)d_in[8];
    const float* W3   = (const float*)d_in[9];
    const float* b3   = (const float*)d_in[10];
    float* out = (float*)d_out;

    fused_kernel<<<GRID, BLOCK>>>(x, W_ih, W_hh, b_ih, b_hh,
                                  W1, b1, W2, b2, W3, b3, out);
    (void)in_sizes; (void)n_in; (void)out_size;
}

// round 15
// speedup vs baseline: 1.0646x; 1.0218x over previous
#include <cuda_runtime.h>
#include <cstdint>

#define FULLMASK 0xffffffffu
typedef unsigned long long ull;

static constexpr int Hh     = 5;
static constexpr int Tt     = 512;
static constexpr int Bb     = 8192;
static constexpr int CHUNK  = 8;            // timesteps per smem chunk
static constexpr int NCHUNK = Tt / CHUNK;   // 64
static constexpr int EPW    = 16;           // elements per warp (2 lanes each)
static constexpr int BLOCK  = 32;
static constexpr int GRID   = Bb / EPW;     // 512 (exact)
static constexpr int ROWF   = Tt * Hh;      // 2560
static constexpr int CH_FL  = CHUNK * Hh;   // 40 floats per element per chunk

// ---------- packed f32x2 helpers ----------
__device__ __forceinline__ ull pack2(float lo, float hi) {
    ull r; asm("mov.b64 %0, {%1, %2};" : "=l"(r) : "f"(lo), "f"(hi)); return r;
}
__device__ __forceinline__ void unpack2(ull v, float& lo, float& hi) {
    asm("mov.b64 {%0, %1}, %2;" : "=f"(lo), "=f"(hi) : "l"(v));
}
__device__ __forceinline__ ull fma2(ull a, ull b, ull c) {
    ull d; asm("fma.rn.f32x2 %0, %1, %2, %3;" : "=l"(d) : "l"(a), "l"(b), "l"(c));
    return d;
}
__device__ __forceinline__ float tanh_fast(float x) {
    float y; asm("tanh.approx.f32 %0, %1;" : "=f"(y) : "f"(x)); return y;
}

// ============================================================================
// Fused LSTM + head. One warp/CTA, 16 elements, 2 lanes/element.
// lane = 2*e + role.  role0 owns pair-rows (i_s, g_s), role1 owns (f_s, o_s).
// R15: BOTH lanes redundantly carry the REAL c_s and hs_s = 2*h_s, so the
// h-projection is fully lane-local (no h-shfl on the chain). Per component:
//   T0 = tanh(z.lo) [Ti|Tf], T1 = tanh(z.hi) [Tg|To]
//   X  = role ? c : T1          (select)
//   pu = fma(T0, X, X)          role0: p = 2ig ; role1: u = 2fc
//   q  = bfly(pu, 1)            exchange p <-> u in ONE bidirectional shfl
//   c' = 0.5*pu + 0.5*q         identical (exact) on both lanes
//   w2 = bfly(T1, 1)            role0 receives To (off-chain, after tanh)
//   OO = role ? T1 : w2         = To on both lanes
//   Tc = tanh(c'); hs = fma(OO, Tc, Tc) = 2h, real on both lanes.
// Sigmoid folding unchanged: i/f/o accs hold z/2, g holds z; hs = 2h.
//   W_ih: i/f/o *0.5, g *1 ; W_hh: i/f/o *0.25, g *0.5 (folded at load).
// x staged as dup (v,v) pairs, padded stride 6 ull -> 2 LDS.128 + 1 LDS.64.
// ============================================================================
__global__ void __launch_bounds__(BLOCK)
fused_kernel(const float* __restrict__ x,
             const float* __restrict__ W_ih, const float* __restrict__ W_hh,
             const float* __restrict__ b_ih, const float* __restrict__ b_hh,
             const float* __restrict__ W1, const float* __restrict__ b1,
             const float* __restrict__ W2, const float* __restrict__ b2,
             const float* __restrict__ W3, const float* __restrict__ b3,
             float* __restrict__ out)
{
    __shared__ __align__(16) ull sx[2][CHUNK][EPW][6];  // padded: 12288 B
    __shared__ float sW1[32 * 5], sb1[32], sb2[32], sb3[5];
    __shared__ float sW2[32 * 33];            // padded rows
    __shared__ float sW3[5 * 33];
    __shared__ float hres[EPW * Hh];

    const int lane = threadIdx.x;
    const int e    = lane >> 1;
    const int role = lane & 1;

    const int base = blockIdx.x * EPW;
    const int gb   = base + e;

    // ---- per-lane packed weights ----
    const int rlo = 5 * role;                 // +0 | +5   (i_s | f_s)
    const int rhi = 10 + 5 * role;            // +10 | +15 (g_s | o_s)
    const float xhi = role ? 0.5f : 1.0f;
    const float hhi = role ? 0.25f : 0.5f;

    ull wx[5][5], wh[5][5], bias[5];
#pragma unroll
    for (int s = 0; s < 5; ++s) {
#pragma unroll
        for (int k = 0; k < 5; ++k) {
            wx[s][k] = pack2(0.50f * W_ih[(s + rlo) * 5 + k],
                             xhi   * W_ih[(s + rhi) * 5 + k]);
            wh[s][k] = pack2(0.25f * W_hh[(s + rlo) * 5 + k],
                             hhi   * W_hh[(s + rhi) * 5 + k]);
        }
        bias[s] = pack2(0.5f * (b_ih[s + rlo] + b_hh[s + rlo]),
                        xhi  * (b_ih[s + rhi] + b_hh[s + rhi]));
    }

    // ---- head weights to smem (one-time) ----
    for (int i = lane; i < 160; i += BLOCK) sW1[i] = W1[i];
    for (int i = lane; i < 1024; i += BLOCK) sW2[(i >> 5) * 33 + (i & 31)] = W2[i];
    for (int i = lane; i < 160; i += BLOCK) sW3[(i >> 5) * 33 + (i & 31)] = W3[i];
    if (lane < 32) { sb1[lane] = b1[lane]; sb2[lane] = b2[lane]; }
    if (lane < 5)  sb3[lane] = b3[lane];

    // ---- staging: lane covers floats [role*20, role*20+20) of its element ----
    const int lo = role * 20;

#define STAGE_LDG(C)                                                          \
    do { const float* src = x + gb * ROWF + (C) * CH_FL + lo;                 \
        pf0 = *(const float4*)(src);                                          \
        pf1 = *(const float4*)(src + 4);                                      \
        pf2 = *(const float4*)(src + 8);                                      \
        pf3 = *(const float4*)(src + 12);                                     \
        pf4 = *(const float4*)(src + 16);                                     \
    } while (0)

#define STAGE_STS(BUF)                                                        \
    do { const float* ap[5] = {&pf0.x, &pf1.x, &pf2.x, &pf3.x, &pf4.x};       \
        _Pragma("unroll")                                                     \
        for (int j = 0; j < 20; ++j) {                                        \
            const float v = ap[j >> 2][j & 3];                                \
            const int f = lo + j, t = f / 5, k = f - 5 * t;                   \
            sx[BUF][t][e][k] = pack2(v, v); }                                 \
    } while (0)

    float4 pf0, pf1, pf2, pf3, pf4;
    STAGE_LDG(0);
    STAGE_STS(0);
    __syncwarp();

    float c[5]  = {0.f, 0.f, 0.f, 0.f, 0.f};   // REAL c on both lanes
    float hs[5] = {0.f, 0.f, 0.f, 0.f, 0.f};   // REAL 2*h on both lanes

    for (int ch = 0; ch < NCHUNK; ++ch) {
        if (ch + 1 < NCHUNK) STAGE_LDG(ch + 1);

        const int buf = ch & 1;
#pragma unroll
        for (int tl = 0; tl < CHUNK; ++tl) {
            const ull* xr = &sx[buf][tl][e][0];

            // pack local h (no shuffle! hs is real on this lane)
            ull hd[5];
#pragma unroll
            for (int k = 0; k < 5; ++k) hd[k] = pack2(hs[k], hs[k]);

            ull a0 = bias[0], a1 = bias[1], a2 = bias[2], a3 = bias[3], a4 = bias[4];

            // x-projection: 2x LDS.128 + 1x LDS.64 (padded 48B stride)
            const ulonglong2 x01 = *(const ulonglong2*)(xr);
            const ulonglong2 x23 = *(const ulonglong2*)(xr + 2);
            const ull        x4  = xr[4];
            a0 = fma2(wx[0][0], x01.x, a0); a1 = fma2(wx[1][0], x01.x, a1);
            a2 = fma2(wx[2][0], x01.x, a2); a3 = fma2(wx[3][0], x01.x, a3);
            a4 = fma2(wx[4][0], x01.x, a4);
            a0 = fma2(wx[0][1], x01.y, a0); a1 = fma2(wx[1][1], x01.y, a1);
            a2 = fma2(wx[2][1], x01.y, a2); a3 = fma2(wx[3][1], x01.y, a3);
            a4 = fma2(wx[4][1], x01.y, a4);
            a0 = fma2(wx[0][2], x23.x, a0); a1 = fma2(wx[1][2], x23.x, a1);
            a2 = fma2(wx[2][2], x23.x, a2); a3 = fma2(wx[3][2], x23.x, a3);
            a4 = fma2(wx[4][2], x23.x, a4);
            a0 = fma2(wx[0][3], x23.y, a0); a1 = fma2(wx[1][3], x23.y, a1);
            a2 = fma2(wx[2][3], x23.y, a2); a3 = fma2(wx[3][3], x23.y, a3);
            a4 = fma2(wx[4][3], x23.y, a4);
            a0 = fma2(wx[0][4], x4,    a0); a1 = fma2(wx[1][4], x4,    a1);
            a2 = fma2(wx[2][4], x4,    a2); a3 = fma2(wx[3][4], x4,    a3);
            a4 = fma2(wx[4][4], x4,    a4);

            // h-projection (chain start — fully local)
#pragma unroll
            for (int k = 0; k < 5; ++k) {
                a0 = fma2(wh[0][k], hd[k], a0);
                a1 = fma2(wh[1][k], hd[k], a1);
                a2 = fma2(wh[2][k], hd[k], a2);
                a3 = fma2(wh[3][k], hd[k], a3);
                a4 = fma2(wh[4][k], hd[k], a4);
            }

            // epilogue: redundant both-lane c/h update
            const ull av[5] = {a0, a1, a2, a3, a4};
            float T0[5], T1[5];
#pragma unroll
            for (int s = 0; s < 5; ++s) {
                float z0, z1; unpack2(av[s], z0, z1);
                T0[s] = tanh_fast(z0);                   // Ti | Tf
                T1[s] = tanh_fast(z1);                   // Tg | To
            }
            float w2[5];
#pragma unroll
            for (int s = 0; s < 5; ++s)                  // off-chain: To to role0
                w2[s] = __shfl_xor_sync(FULLMASK, T1[s], 1);
            float pu[5];
#pragma unroll
            for (int s = 0; s < 5; ++s) {
                const float X = role ? c[s] : T1[s];     // select
                pu[s] = fmaf(T0[s], X, X);               // p=2ig | u=2fc
            }
            float q[5];
#pragma unroll
            for (int s = 0; s < 5; ++s)                  // p <-> u, one bfly
                q[s] = __shfl_xor_sync(FULLMASK, pu[s], 1);
#pragma unroll
            for (int s = 0; s < 5; ++s)                  // identical on both lanes
                c[s] = fmaf(0.5f, pu[s], 0.5f * q[s]);
            float Tc[5];
#pragma unroll
            for (int s = 0; s < 5; ++s)
                Tc[s] = tanh_fast(c[s]);
#pragma unroll
            for (int s = 0; s < 5; ++s) {
                const float OO = role ? T1[s] : w2[s];   // To on both lanes
                hs[s] = fmaf(OO, Tc[s], Tc[s]);          // real 2h on both lanes
            }
        }

        if (ch + 1 < NCHUNK) STAGE_STS((ch + 1) & 1);
        __syncwarp();
    }

    // ==================== fused head ====================
    if (role == 1) {
#pragma unroll
        for (int s = 0; s < 5; ++s)
            hres[e * Hh + s] = 0.5f * hs[s] + x[gb * ROWF + (Tt - 1) * Hh + s];
    }
    __syncwarp();

#pragma unroll 4
    for (int ee = 0; ee < EPW; ++ee) {
        const int g = base + ee;
        float a1 = sb1[lane];
#pragma unroll
        for (int k = 0; k < 5; ++k)
            a1 = fmaf(sW1[lane * 5 + k], hres[ee * Hh + k], a1);
        a1 = fmaxf(a1, 0.0f);

        float a2 = sb2[lane];
#pragma unroll
        for (int k = 0; k < 32; ++k)
            a2 = fmaf(sW2[lane * 33 + k], __shfl_sync(FULLMASK, a1, k), a2);
        a2 = fmaxf(a2, 0.0f);

        const int wrow = (lane < 5) ? lane : 0;
        float o = (lane < 5) ? sb3[lane] : 0.0f;
#pragma unroll
        for (int k = 0; k < 32; ++k)
            o = fmaf(sW3[wrow * 33 + k], __shfl_sync(FULLMASK, a2, k), o);

        if (lane < 5) out[g * Hh + lane] = o;
    }

#undef STAGE_LDG
#undef STAGE_STS
}

// ============================================================================
extern "C" void kernel_launch(void* const* d_in, const int* in_sizes, int n_in,
                              void* d_out, int out_size) {
    const float* x    = (const float*)d_in[0];
    const float* W_ih = (const float*)d_in[1];
    const float* W_hh = (const float*)d_in[2];
    const float* b_ih = (const float*)d_in[3];
    const float* b_hh = (const float*)d_in[4];
    const float* W1   = (const float*)d_in[5];
    const float* b1   = (const float*)d_in[6];
    const float* W2   = (const float*)d_in[7];
    const float* b2   = (const float*)d_in[8];
    const float* W3   = (const float*)d_in[9];
    const float* b3   = (const float*)d_in[10];
    float* out = (float*)d_out;

    fused_kernel<<<GRID, BLOCK>>>(x, W_ih, W_hh, b_ih, b_hh,
                                  W1, b1, W2, b2, W3, b3, out);
    (void)in_sizes; (void)n_in; (void)out_size;
}